// round 17
// baseline (speedup 1.0000x reference)
#include <cuda_runtime.h>
#include <cuda_bf16.h>
#include <cuda_fp16.h>
#include <math.h>
#include <stdint.h>

// Problem dims (fixed)
#define BB   2
#define SQ   512
#define SKK  512
#define EE   512
#define HH   256
#define MR   1024            // B*SQ = B*SK
#define NTOT (BB*SQ*SKK)     // 524288

// ---------------- scratch (device globals; no allocation allowed) -------------
__device__ float g_qf [MR*HH];
__device__ float g_kf [MR*HH];
__device__ float g_qp [MR*HH];
__device__ float g_vq [MR*HH];
__device__ float g_kpT[HH*MR];   // [H][B*SK]
__device__ float g_vkT[HH*MR];   // [H][B*SK]
// fp16 weight images: word layout [layer][k][nw] (nw = n/2, f16x2)
__device__ __align__(16) uint32_t g_Wh[2 * 256 * 128];

// SMEM map (byte offsets from 1024-aligned base)  -- main kernel
#define SM_A   0u        // 128 rows x 512B  (fp16 A) = 64KB
#define SM_W   65536u    // 256 rows x 512B  (full weight layer, fp16) = 128KB
#define SM_VEC 196608u
#define SMEM_BYTES (206848 + 1024)

// proj kernel dynamic smem: As 3 x (32*36) + Ws 3 x (32*64) floats
#define PROJ_AS_STRIDE 1152
#define PROJ_WS_STRIDE 2048
#define PROJ_WS_OFF    (3 * PROJ_AS_STRIDE)
#define PROJ_SMEM_BYTES ((3 * PROJ_AS_STRIDE + 3 * PROJ_WS_STRIDE) * 4)

// ---------------- PTX helpers --------------------------------------------------
__device__ __forceinline__ uint32_t smem_u32(const void* p) {
    return (uint32_t)__cvta_generic_to_shared(p);
}
__device__ __forceinline__ void ldsm_x4(uint32_t (&r)[4], uint32_t addr) {
    asm volatile("ldmatrix.sync.aligned.m8n8.x4.shared.b16 {%0,%1,%2,%3}, [%4];"
        : "=r"(r[0]), "=r"(r[1]), "=r"(r[2]), "=r"(r[3]) : "r"(addr));
}
__device__ __forceinline__ void ldsm_x4_t(uint32_t (&r)[4], uint32_t addr) {
    asm volatile("ldmatrix.sync.aligned.m8n8.x4.trans.shared.b16 {%0,%1,%2,%3}, [%4];"
        : "=r"(r[0]), "=r"(r[1]), "=r"(r[2]), "=r"(r[3]) : "r"(addr));
}
__device__ __forceinline__ void mma_f16(float (&d)[4], const uint32_t (&a)[4],
                                        uint32_t b0, uint32_t b1) {
    asm volatile("mma.sync.aligned.m16n8k16.row.col.f32.f16.f16.f32 "
        "{%0,%1,%2,%3}, {%4,%5,%6,%7}, {%8,%9}, {%0,%1,%2,%3};"
        : "+f"(d[0]), "+f"(d[1]), "+f"(d[2]), "+f"(d[3])
        : "r"(a[0]), "r"(a[1]), "r"(a[2]), "r"(a[3]), "r"(b0), "r"(b1));
}
__device__ __forceinline__ unsigned long long pack_dup(float a) {
    unsigned long long r;
    asm("mov.b64 %0, {%1, %1};" : "=l"(r) : "f"(a));
    return r;
}
__device__ __forceinline__ void unpack2(unsigned long long v, float& lo, float& hi) {
    asm("mov.b64 {%0, %1}, %2;" : "=f"(lo), "=f"(hi) : "l"(v));
}
__device__ __forceinline__ void ffma2(unsigned long long& acc, unsigned long long a,
                                      unsigned long long b) {
    asm("fma.rn.f32x2 %0, %1, %2, %0;" : "+l"(acc) : "l"(a), "l"(b));
}

// ---------------- small math helpers ------------------------------------------
__device__ __forceinline__ uint32_t f16x2bits(float v0, float v1) {
    __half2 h = __floats2half2_rn(v0, v1);
    return *reinterpret_cast<uint32_t*>(&h);
}
__device__ __forceinline__ float softplusf(float x) {
    if (x > 20.f) return x;
    return log1pf(expf(x));
}

// ---------------- prologue: batched 1024x256 projection GEMM -------------------
// 32x64 tiles, K-chunk 32, 3-stage cp.async pipeline, ONE barrier per chunk.
// blockIdx.z == wsplitZ runs the weight-convert instead (merged launch).
struct ProjJob {
    const float* A; const float* W; const float* bias; float* C;
    int wrow0; int doRelu; int doTrans;
};

__device__ __forceinline__ void proj_stage_chunk(const float* __restrict__ A,
                                                 const float* __restrict__ W,
                                                 int K, int wrow0, int m0, int n0,
                                                 int c, float* As, float* Ws,
                                                 int tid)
{
    const int kc = c << 5;
    const int buf = c % 3;
    const uint32_t asb = smem_u32(As + buf * PROJ_AS_STRIDE);
    const uint32_t wsb = smem_u32(Ws + buf * PROJ_WS_STRIDE);
    // A chunk: 32 rows x 32 floats (8 x 16B per row); 1 unit/thread
    {
        int m = tid >> 3, seg = tid & 7;
        const float* src = A + (m0 + m) * K + kc + seg * 4;
        uint32_t dst = asb + (uint32_t)(m * 36 + seg * 4) * 4u;
        asm volatile("cp.async.cg.shared.global [%0], [%1], 16;"
                     :: "r"(dst), "l"(src));
    }
    // W chunk: 32 k-rows x 64 floats (16 x 16B per row); 2 units/thread
    #pragma unroll
    for (int i = 0; i < 2; i++) {
        int e = tid + i * 256;              // 0..511
        int kk = e >> 4, seg = e & 15;
        const float* src = W + (wrow0 + kc + kk) * 256 + n0 + seg * 4;
        uint32_t dst = wsb + (uint32_t)(kk * 64 + seg * 4) * 4u;
        asm volatile("cp.async.cg.shared.global [%0], [%1], 16;"
                     :: "r"(dst), "l"(src));
    }
    asm volatile("cp.async.commit_group;" ::: "memory");
}

__global__ __launch_bounds__(256)
void proj_batch_kernel(ProjJob j0, ProjJob j1, ProjJob j2, ProjJob j3, int K,
                       const float* __restrict__ Wc2,
                       const float* __restrict__ Wc3, int wsplitZ)
{
    const int tid = threadIdx.x;
    if ((int)blockIdx.z == wsplitZ) {
        // weight convert: 65536 items strided over all z-slice blocks
        int nblk  = gridDim.x * gridDim.y;
        int base  = (blockIdx.y * gridDim.x + blockIdx.x) * 256 + tid;
        int strd  = nblk * 256;
        for (int idx = base; idx < 65536; idx += strd) {
            int layer = idx >> 15;
            int rem   = idx & 32767;
            int k  = rem >> 7;
            int nw = rem & 127;
            const float* W = layer ? Wc3 : Wc2;
            g_Wh[idx] = f16x2bits(W[k * 256 + nw * 2], W[k * 256 + nw * 2 + 1]);
        }
        return;
    }
    ProjJob jb = (blockIdx.z == 0) ? j0 : (blockIdx.z == 1) ? j1 :
                 (blockIdx.z == 2) ? j2 : j3;
    extern __shared__ float psm[];
    float* As = psm;                    // 3 bufs x 32x36
    float* Ws = psm + PROJ_WS_OFF;      // 3 bufs x 32x64
    const int m0  = blockIdx.y * 32;
    const int n0  = blockIdx.x * 64;
    const int ty  = tid >> 4, tx = tid & 15;

    unsigned long long acc2[2][2] = {{0ull, 0ull}, {0ull, 0ull}};
    const int nch = K >> 5;

    proj_stage_chunk(jb.A, jb.W, K, jb.wrow0, m0, n0, 0, As, Ws, tid);
    proj_stage_chunk(jb.A, jb.W, K, jb.wrow0, m0, n0, 1, As, Ws, tid);

    for (int ch = 0; ch < nch; ch++) {
        if (ch + 1 < nch) { asm volatile("cp.async.wait_group 1;" ::: "memory"); }
        else              { asm volatile("cp.async.wait_group 0;" ::: "memory"); }
        __syncthreads();
        if (ch + 2 < nch)
            proj_stage_chunk(jb.A, jb.W, K, jb.wrow0, m0, n0, ch + 2, As, Ws, tid);

        const float* Ab = As + (ch % 3) * PROJ_AS_STRIDE;
        const float* Wb = Ws + (ch % 3) * PROJ_WS_STRIDE;
        #pragma unroll
        for (int k4 = 0; k4 < 32; k4 += 4) {
            float4 a0 = *(const float4*)&Ab[(ty * 2) * 36 + k4];
            float4 a1 = *(const float4*)&Ab[(ty * 2 + 1) * 36 + k4];
            float a0v[4] = {a0.x, a0.y, a0.z, a0.w};
            float a1v[4] = {a1.x, a1.y, a1.z, a1.w};
            #pragma unroll
            for (int kk = 0; kk < 4; kk++) {
                const float* wr = &Wb[(k4 + kk) * 64 + tx * 4];
                unsigned long long w01 = *(const unsigned long long*)wr;
                unsigned long long w23 = *(const unsigned long long*)(wr + 2);
                unsigned long long a0d = pack_dup(a0v[kk]);
                unsigned long long a1d = pack_dup(a1v[kk]);
                ffma2(acc2[0][0], a0d, w01);
                ffma2(acc2[0][1], a0d, w23);
                ffma2(acc2[1][0], a1d, w01);
                ffma2(acc2[1][1], a1d, w23);
            }
        }
    }
    #pragma unroll
    for (int i = 0; i < 2; i++) {
        float vout[4];
        unpack2(acc2[i][0], vout[0], vout[1]);
        unpack2(acc2[i][1], vout[2], vout[3]);
        const int r = m0 + ty * 2 + i;
        #pragma unroll
        for (int j = 0; j < 4; j++) {
            const int n = n0 + tx * 4 + j;
            float v = vout[j] + (jb.bias ? jb.bias[n] : 0.f);
            if (jb.doRelu) v = fmaxf(v, 0.f);
            if (jb.doTrans) jb.C[n * MR + r] = v;
            else            jb.C[r * 256 + n] = v;
        }
    }
}

// ---------------- main pairwise-MLP kernel (fp16 mma, split-layer W copies) ----

// copy HALF of a weight layer (64KB, rows half*128..half*128+127) into SM_W
__device__ __forceinline__ void cp_half(const char* __restrict__ src,
                                        uint32_t dstbase, int half, int tid)
{
    const char* s = src + half * 65536;
    #pragma unroll
    for (int i = 0; i < 8; i++) {
        int e = tid + i * 512;                 // 0..4095
        int kl = e >> 5, u = e & 31;           // local row (0..127), 16B unit
        int k = kl + half * 128;               // global row
        uint32_t d = dstbase + (uint32_t)k * 512u + (uint32_t)((u ^ (k & 7)) << 4);
        asm volatile("cp.async.cg.shared.global [%0], [%1], 16;"
                     :: "r"(d), "l"(s + e * 16));
    }
    asm volatile("cp.async.commit_group;" ::: "memory");
}

// build 2 adjacent 16B units (g0, g0+1) of one A row: j0 = 8*g0 + quad*2
__device__ __forceinline__ void a_store_units(char* smp, int m, int quad, int g0,
                                              float v0, float v1, float v2, float v3)
{
    char* arow = smp + (uint32_t)m * 512u;
    uint32_t off0 = (uint32_t)(((g0 ^ (m & 7)) << 4) + quad * 4);
    *(uint32_t*)(arow + SM_A + off0) = f16x2bits(v0, v1);
    uint32_t off1 = (uint32_t)((((g0 + 1) ^ (m & 7)) << 4) + quad * 4);
    *(uint32_t*)(arow + SM_A + off1) = f16x2bits(v2, v3);
}

// Half of a 128x256x256 fp16 GEMM: 8 k16 steps starting at k16_0 (0 or 8).
// BUILD: builds A slice k16 = i+8 during iteration i (valid only for k16_0=0,
//        with a __syncthreads between the two halves).
// VAR:   accumulates 4 variance-dot terms per iteration, j = quad*64+vbase+i*4.
template<bool BUILD, bool VAR>
__device__ __forceinline__ void gemm_half(uint32_t abase, int k16_0,
                                          int warpM, int warpN, int lane,
                                          float (&acc)[2][8][4],
                                          char* smp, const float* __restrict__ qpb,
                                          const float* __restrict__ vqb,
                                          const float* __restrict__ wv2s,
                                          int rowb, float& vacc,
                                          int quad, int m, int vbase)
{
    const int rit  = (lane & 7) | (((lane >> 3) & 1) << 3); // row within 16-tile
    const int koff = lane >> 4;                              // 0/1: unit select
    uint32_t a_row[2]; uint32_t a_sw[2];
    #pragma unroll
    for (int mt = 0; mt < 2; mt++) {
        int rr = warpM * 32 + mt * 16 + rit;
        a_row[mt] = abase + (uint32_t)rr * 512u;
        a_sw[mt]  = (uint32_t)(rr & 7);
    }
    const uint32_t ksw = (uint32_t)(rit & 7);
    uint32_t boff[4];
    #pragma unroll
    for (int np = 0; np < 4; np++) {
        uint32_t nunit = (uint32_t)(warpN * 8 + np * 2 + koff);
        boff[np] = ((nunit ^ ksw) << 4);
    }
    const uint32_t browbase = abase + SM_W + (uint32_t)rit * 512u;

    // fragment double buffers: parity = i & 1 (k16_0 is even)
    uint32_t aF[2][2][4];
    uint32_t bF[2][2][4];
    #pragma unroll
    for (int mt = 0; mt < 2; mt++)
        ldsm_x4(aF[0][mt],
                a_row[mt] + (((uint32_t)(k16_0 * 2 + koff) ^ a_sw[mt]) << 4));
    {
        const uint32_t br0 = browbase + (uint32_t)k16_0 * 8192u;
        ldsm_x4_t(bF[0][0], br0 + boff[0]);
        ldsm_x4_t(bF[0][1], br0 + boff[1]);
    }

    #pragma unroll
    for (int i = 0; i < 8; i++) {
        const int k16 = k16_0 + i;
        const int s = i & 1;

        // ---- early global loads (latency hidden behind MMAs) ----
        float kp0, kp1, kp2, kp3;
        float vk0, vk1, vk2, vk3;
        int j0 = 0, jv = 0;
        if (BUILD) {
            int g0 = 2 * (i + 8);
            j0 = 8 * g0 + quad * 2;
            kp0 = g_kpT[j0 * MR + rowb];
            kp1 = g_kpT[(j0 + 1) * MR + rowb];
            kp2 = g_kpT[(j0 + 8) * MR + rowb];
            kp3 = g_kpT[(j0 + 9) * MR + rowb];
        }
        if (VAR) {
            jv = quad * 64 + vbase + i * 4;
            vk0 = g_vkT[jv * MR + rowb];
            vk1 = g_vkT[(jv + 1) * MR + rowb];
            vk2 = g_vkT[(jv + 2) * MR + rowb];
            vk3 = g_vkT[(jv + 3) * MR + rowb];
        }

        // ---- B np=2,3 for current k16 ----
        uint32_t bT[2][4];
        const uint32_t brow = browbase + (uint32_t)k16 * 8192u;
        ldsm_x4_t(bT[0], brow + boff[2]);
        ldsm_x4_t(bT[1], brow + boff[3]);

        // ---- MMA np=0,1 with pre-loaded fragments ----
        #pragma unroll
        for (int mt = 0; mt < 2; mt++) {
            mma_f16(acc[mt][0], aF[s][mt], bF[s][0][0], bF[s][0][1]);
            mma_f16(acc[mt][1], aF[s][mt], bF[s][0][2], bF[s][0][3]);
            mma_f16(acc[mt][2], aF[s][mt], bF[s][1][0], bF[s][1][1]);
            mma_f16(acc[mt][3], aF[s][mt], bF[s][1][2], bF[s][1][3]);
        }

        // ---- prefetch fragments for k16+1 (within this half only) ----
        if (i < 7) {
            #pragma unroll
            for (int mt = 0; mt < 2; mt++) {
                uint32_t unit = (uint32_t)((k16 + 1) * 2 + koff);
                ldsm_x4(aF[s ^ 1][mt], a_row[mt] + ((unit ^ a_sw[mt]) << 4));
            }
            const uint32_t brown = browbase + (uint32_t)(k16 + 1) * 8192u;
            ldsm_x4_t(bF[s ^ 1][0], brown + boff[0]);
            ldsm_x4_t(bF[s ^ 1][1], brown + boff[1]);
        }

        // ---- MMA np=2,3 ----
        #pragma unroll
        for (int mt = 0; mt < 2; mt++) {
            mma_f16(acc[mt][4], aF[s][mt], bT[0][0], bT[0][1]);
            mma_f16(acc[mt][5], aF[s][mt], bT[0][2], bT[0][3]);
            mma_f16(acc[mt][6], aF[s][mt], bT[1][0], bT[1][1]);
            mma_f16(acc[mt][7], aF[s][mt], bT[1][2], bT[1][3]);
        }

        // ---- late: A-build stores + variance FMAs ----
        if (BUILD) {
            int g0 = 2 * (i + 8);
            float v0 = fmaxf(qpb[j0]     + kp0, 0.f);
            float v1 = fmaxf(qpb[j0 + 1] + kp1, 0.f);
            float v2 = fmaxf(qpb[j0 + 8] + kp2, 0.f);
            float v3 = fmaxf(qpb[j0 + 9] + kp3, 0.f);
            a_store_units(smp, m, quad, g0, v0, v1, v2, v3);
        }
        if (VAR) {
            vacc = fmaf(fmaxf(vqb[jv]     + vk0, 0.f), wv2s[jv],     vacc);
            vacc = fmaf(fmaxf(vqb[jv + 1] + vk1, 0.f), wv2s[jv + 1], vacc);
            vacc = fmaf(fmaxf(vqb[jv + 2] + vk2, 0.f), wv2s[jv + 2], vacc);
            vacc = fmaf(fmaxf(vqb[jv + 3] + vk3, 0.f), wv2s[jv + 3], vacc);
        }
    }
}

__global__ __launch_bounds__(512, 1)
void pair_mma_kernel(const float* __restrict__ b1,  const float* __restrict__ b2,
                     const float* __restrict__ b3,  const float* __restrict__ Wf,
                     const float* __restrict__ bfp, const float* __restrict__ bv1,
                     const float* __restrict__ Wv2, const float* __restrict__ bv2,
                     float* __restrict__ out)
{
    extern __shared__ char smraw[];
    const uint32_t smbase = smem_u32(smraw);
    const uint32_t abase  = (smbase + 1023u) & ~1023u;
    char* smp = smraw + (abase - smbase);
    float* qpb  = (float*)(smp + SM_VEC);
    float* vqb  = qpb + 256;
    float* b2s  = vqb + 256;
    float* b3s  = b2s + 256;
    float* wfs  = b3s + 256;
    float* wv2s = wfs + 256;
    float* red  = wv2s + 256;   // 512 floats: [row][warpN]
    float* vred = red + 512;    // 512 floats: [key][p]

    const int tid   = threadIdx.x;
    const int lane  = tid & 31;
    const int w     = tid >> 5;
    const int warpM = w & 3, warpN = w >> 2;
    const int quad  = tid >> 7;
    const int m     = tid & 127;
    const int bid = blockIdx.x;
    const int kt  = bid & 3;
    const int q   = (bid >> 2) & 511;
    const int b   = bid >> 11;
    const int k0  = kt << 7;
    const int rowb  = b * SKK + k0 + m;
    const int lbase = (b * SQ + q) * SKK + k0;

    const char* W2src = (const char*)g_Wh;
    const char* W3src = (const char*)g_Wh + 131072;

    // start W2 copy immediately as two 64KB halves (groups 0,1)
    cp_half(W2src, abase + SM_W, 0, tid);
    cp_half(W2src, abase + SM_W, 1, tid);

    // vectors
    {
        const int r = (b * SQ + q) * HH;
        if (tid < 256) {
            qpb[tid] = g_qp[r + tid] + b1[tid];
            b2s[tid] = b2[tid];
            wfs[tid] = Wf[tid];
        } else {
            int u = tid & 255;
            vqb[u]  = g_vq[r + u] + bv1[u];
            b3s[u]  = b3[u];
            wv2s[u] = Wv2[u];
        }
    }
    __syncthreads();

    // ---- prebuild A slices k16 0..7 only, overlapping the W2 copy ----
    {
        #pragma unroll 4
        for (int gg = 0; gg < 8; gg++) {
            int g0 = gg * 2;
            int j0 = 8 * g0 + quad * 2;
            float v0 = fmaxf(qpb[j0]     + g_kpT[j0 * MR + rowb],       0.f);
            float v1 = fmaxf(qpb[j0 + 1] + g_kpT[(j0 + 1) * MR + rowb], 0.f);
            float v2 = fmaxf(qpb[j0 + 8] + g_kpT[(j0 + 8) * MR + rowb], 0.f);
            float v3 = fmaxf(qpb[j0 + 9] + g_kpT[(j0 + 9) * MR + rowb], 0.f);
            a_store_units(smp, m, quad, g0, v0, v1, v2, v3);
        }
    }
    asm volatile("cp.async.wait_group 1;" ::: "memory");   // W2-lo ready
    __syncthreads();

    // ---- GEMM 1: D = h0 @ W2 ----
    float acc[2][8][4];
    #pragma unroll
    for (int i = 0; i < 2; i++)
        #pragma unroll
        for (int j = 0; j < 8; j++)
            #pragma unroll
            for (int e = 0; e < 4; e++) acc[i][j][e] = 0.f;
    float vacc = 0.f;
    // half1 (k16 0..7, W2 rows 0..127): builds A k16 8..15 + variance j 0..31
    gemm_half<true, true>(abase, 0, warpM, warpN, lane, acc,
                          smp, qpb, vqb, wv2s, rowb, vacc, quad, m, 0);
    asm volatile("cp.async.wait_group 0;" ::: "memory");   // W2-hi ready
    __syncthreads();   // A k16 8..15 visible; W2-lo reads all done
    // W2-lo dead -> stream W3-lo in during half2 (group 2)
    cp_half(W3src, abase + SM_W, 0, tid);
    // half2 (k16 8..15, W2 rows 128..255): variance j 32..63
    gemm_half<false, true>(abase, 8, warpM, warpN, lane, acc,
                           smp, qpb, vqb, wv2s, rowb, vacc, quad, m, 32);
    vred[m * 4 + quad] = vacc;
    __syncthreads();   // all W2 + h0 reads done; vred complete

    // W2-hi dead -> stream W3-hi in during epilogue (group 3)
    cp_half(W3src, abase + SM_W, 1, tid);

    // variance finalize
    if (tid < 128) {
        float s = vred[tid * 4] + vred[tid * 4 + 1] + vred[tid * 4 + 2] + vred[tid * 4 + 3]
                  + bv2[0];
        out[NTOT + lbase + tid] = softplusf(s);
    }

    // ---- epilogue 1: h1 = relu(D + b2) -> A buffer (fp16) ----
    {
        const int g  = lane >> 2;
        const int tg = lane & 3;
        #pragma unroll
        for (int mt = 0; mt < 2; mt++) {
            int r0 = warpM * 32 + mt * 16 + g;
            int r1 = r0 + 8;
            uint32_t row0 = (uint32_t)r0 * 512u;
            uint32_t row1 = (uint32_t)r1 * 512u;
            #pragma unroll
            for (int nt = 0; nt < 8; nt++) {
                int c0 = warpN * 64 + nt * 8 + tg * 2;
                float b20 = b2s[c0], b21 = b2s[c0 + 1];
                float v00 = fmaxf(acc[mt][nt][0] + b20, 0.f);
                float v01 = fmaxf(acc[mt][nt][1] + b21, 0.f);
                float v10 = fmaxf(acc[mt][nt][2] + b20, 0.f);
                float v11 = fmaxf(acc[mt][nt][3] + b21, 0.f);
                uint32_t unit = (uint32_t)(c0 >> 3);
                uint32_t o0 = row0 + ((unit ^ (uint32_t)(r0 & 7)) << 4) + (uint32_t)(tg * 4);
                uint32_t o1 = row1 + ((unit ^ (uint32_t)(r1 & 7)) << 4) + (uint32_t)(tg * 4);
                *(uint32_t*)(smp + SM_A + o0) = f16x2bits(v00, v01);
                *(uint32_t*)(smp + SM_A + o1) = f16x2bits(v10, v11);
            }
        }
    }
    asm volatile("cp.async.wait_group 1;" ::: "memory");   // W3-lo ready
    __syncthreads();

    // ---- GEMM 2: D = h1 @ W3 ----
    #pragma unroll
    for (int i = 0; i < 2; i++)
        #pragma unroll
        for (int j = 0; j < 8; j++)
            #pragma unroll
            for (int e = 0; e < 4; e++) acc[i][j][e] = 0.f;
    gemm_half<false, false>(abase, 0, warpM, warpN, lane, acc,
                            smp, qpb, vqb, wv2s, rowb, vacc, quad, m, 0);
    asm volatile("cp.async.wait_group 0;" ::: "memory");   // W3-hi ready
    __syncthreads();
    gemm_half<false, false>(abase, 8, warpM, warpN, lane, acc,
                            smp, qpb, vqb, wv2s, rowb, vacc, quad, m, 0);

    // ---- epilogue 2: logit = relu(D + b3) . Wf, cross-warp reduce ----
    {
        const int g  = lane >> 2;
        const int tg = lane & 3;
        #pragma unroll
        for (int mt = 0; mt < 2; mt++) {
            float lg0 = 0.f, lg1 = 0.f;
            #pragma unroll
            for (int nt = 0; nt < 8; nt++) {
                int c0 = warpN * 64 + nt * 8 + tg * 2;
                float b30 = b3s[c0], b31 = b3s[c0 + 1];
                float w0  = wfs[c0], w1  = wfs[c0 + 1];
                lg0 = fmaf(fmaxf(acc[mt][nt][0] + b30, 0.f), w0, lg0);
                lg0 = fmaf(fmaxf(acc[mt][nt][1] + b31, 0.f), w1, lg0);
                lg1 = fmaf(fmaxf(acc[mt][nt][2] + b30, 0.f), w0, lg1);
                lg1 = fmaf(fmaxf(acc[mt][nt][3] + b31, 0.f), w1, lg1);
            }
            lg0 += __shfl_xor_sync(0xffffffffu, lg0, 1);
            lg0 += __shfl_xor_sync(0xffffffffu, lg0, 2);
            lg1 += __shfl_xor_sync(0xffffffffu, lg1, 1);
            lg1 += __shfl_xor_sync(0xffffffffu, lg1, 2);
            if (tg == 0) {
                int r0 = warpM * 32 + mt * 16 + g;
                red[r0 * 4 + warpN]       = lg0;
                red[(r0 + 8) * 4 + warpN] = lg1;
            }
        }
    }
    __syncthreads();
    if (tid < 128) {
        float s = red[tid * 4] + red[tid * 4 + 1] + red[tid * 4 + 2] + red[tid * 4 + 3]
                  + bfp[0];
        out[lbase + tid] = s;
    }
}

// ---------------- launcher -----------------------------------------------------
extern "C" void kernel_launch(void* const* d_in, const int* in_sizes, int n_in,
                              void* d_out, int out_size)
{
    const float* query = (const float*)d_in[0];
    const float* key   = (const float*)d_in[1];
    const float* Wqe   = (const float*)d_in[2];
    const float* bqe   = (const float*)d_in[3];
    const float* Wke   = (const float*)d_in[4];
    const float* bke   = (const float*)d_in[5];
    const float* W1    = (const float*)d_in[6];
    const float* b1    = (const float*)d_in[7];
    const float* W2    = (const float*)d_in[8];
    const float* b2    = (const float*)d_in[9];
    const float* W3    = (const float*)d_in[10];
    const float* b3    = (const float*)d_in[11];
    const float* Wf    = (const float*)d_in[12];
    const float* bf    = (const float*)d_in[13];
    const float* Wv1   = (const float*)d_in[14];
    const float* bv1   = (const float*)d_in[15];
    const float* Wv2   = (const float*)d_in[16];
    const float* bv2   = (const float*)d_in[17];
    float* out = (float*)d_out;

    void *p_qf, *p_kf, *p_qp, *p_vq, *p_kpT, *p_vkT;
    cudaGetSymbolAddress(&p_qf,  g_qf);
    cudaGetSymbolAddress(&p_kf,  g_kf);
    cudaGetSymbolAddress(&p_qp,  g_qp);
    cudaGetSymbolAddress(&p_vq,  g_vq);
    cudaGetSymbolAddress(&p_kpT, g_kpT);
    cudaGetSymbolAddress(&p_vkT, g_vkT);

    cudaFuncSetAttribute(proj_batch_kernel,
                         cudaFuncAttributeMaxDynamicSharedMemorySize, PROJ_SMEM_BYTES);

    // launch 1: encoders (z=0,1) + weight convert (z=2); 32-row M tiles
    ProjJob e0 { query, Wqe, bqe, (float*)p_qf, 0, 1, 0 };
    ProjJob e1 { key,   Wke, bke, (float*)p_kf, 0, 1, 0 };
    proj_batch_kernel<<<dim3(4, 32, 3), 256, PROJ_SMEM_BYTES>>>(
        e0, e1, e0, e0, EE, W2, W3, 2);

    // launch 2: stage-2 projections
    ProjJob s0 { (const float*)p_qf, W1,  nullptr, (float*)p_qp,  0,   0, 0 };
    ProjJob s1 { (const float*)p_kf, W1,  nullptr, (float*)p_kpT, 256, 0, 1 };
    ProjJob s2 { (const float*)p_qf, Wv1, nullptr, (float*)p_vq,  0,   0, 0 };
    ProjJob s3 { (const float*)p_kf, Wv1, nullptr, (float*)p_vkT, 256, 0, 1 };
    proj_batch_kernel<<<dim3(4, 32, 4), 256, PROJ_SMEM_BYTES>>>(
        s0, s1, s2, s3, HH, W2, W3, -1);

    // launch 3: main fused pairwise-MLP kernel (split-layer W streaming)
    cudaFuncSetAttribute(pair_mma_kernel,
                         cudaFuncAttributeMaxDynamicSharedMemorySize, SMEM_BYTES);
    pair_mma_kernel<<<BB * SQ * (SKK / 128), 512, SMEM_BYTES>>>(
        b1, b2, b3, Wf, bf, bv1, Wv2, bv2, out);
}